// round 12
// baseline (speedup 1.0000x reference)
#include <cuda_runtime.h>
#include <cuda_bf16.h>

#define NB    512
#define DIN   128
#define DH    256
#define COUT  0
#define GRID  164
#define NTH   256

// Scratch (fp32 features)
__device__ float g_H1[2][NB * DH];
__device__ float g_H2[2][NB * DH];
__device__ float g_D1[2][NB * DH];
__device__ float g_D2[2][NB * DH];
__device__ float g_invn[2][NB];
__device__ float g_S[5][NB * NB];   // 0:Sx 1:Sh1 2:Sh2 3:Sd1 4:Sd2

// bf16 split features, row stride 256 for all (x uses first 128 cols)
__device__ __nv_bfloat16 g_Fhi[5][2][NB * DH];
__device__ __nv_bfloat16 g_Flo[5][2][NB * DH];

// Global barrier counters (monotonic; generation = count/GRID, no reset needed)
__device__ unsigned g_barc[8];

__device__ __forceinline__ void gbar(int k) {
    __syncthreads();
    if (threadIdx.x == 0) {
        __threadfence();
        unsigned my = atomicAdd(&g_barc[k], 1u);
        unsigned target = (my / GRID + 1u) * GRID;
        while (*(volatile unsigned*)&g_barc[k] < target) {}
    }
    __syncthreads();
}

// ---------------------------------------------------------------------------
__device__ __forceinline__ void split4(float4 v, __nv_bfloat16* hi,
                                       __nv_bfloat16* lo, int off) {
    float f[4] = {v.x, v.y, v.z, v.w};
    __nv_bfloat16 h[4], l[4];
#pragma unroll
    for (int c = 0; c < 4; c++) {
        h[c] = __float2bfloat16_rn(f[c]);
        l[c] = __float2bfloat16_rn(f[c] - __bfloat162float(h[c]));
    }
    __nv_bfloat162 h01{h[0], h[1]}, h23{h[2], h[3]};
    __nv_bfloat162 l01{l[0], l[1]}, l23{l[2], l[3]};
    uint2 uh, ul;
    uh.x = *(unsigned*)&h01; uh.y = *(unsigned*)&h23;
    ul.x = *(unsigned*)&l01; ul.y = *(unsigned*)&l23;
    *(uint2*)&hi[off] = uh;
    *(uint2*)&lo[off] = ul;
}

__device__ __forceinline__ void split1(float v, __nv_bfloat16* hi,
                                       __nv_bfloat16* lo, int off) {
    __nv_bfloat16 h = __float2bfloat16_rn(v);
    hi[off] = h;
    lo[off] = __float2bfloat16_rn(v - __bfloat162float(h));
}

__device__ __forceinline__ float sq4(float4 v) {
    return fmaf(v.x, v.x, fmaf(v.y, v.y, fmaf(v.z, v.z, v.w * v.w)));
}

// ===========================================================================
// Feature phase (R4 proven body): 32x64 tile, 256 threads, KT=32, micro 2x4.
// 128 work units: side = cta>>6; rem = cta&63; i-tile rem>>2; n-tile rem&3.
// ===========================================================================
template <int MODE>
__device__ void feat_phase(char* sm, int cta,
                           const float* __restrict__ x1, const float* __restrict__ x2,
                           const float* __restrict__ W1, const float* __restrict__ b1,
                           const float* __restrict__ W2, const float* __restrict__ b2,
                           const float* __restrict__ W3)
{
    if (cta >= 128) return;
    float* As = (float*)sm;             // [2][32][34] = 8704B
    float* Bs = (float*)(sm + 8704);    // [2][32][68] = 17408B
    const int tid = threadIdx.x;
    const int side = cta >> 6;
    const int rem = cta & 63;
    const int i0 = (rem >> 2) * 32;
    const int n0 = (rem & 3) * 64;
    const int ti = tid >> 4;
    const int tj = tid & 15;

    const float* __restrict__ Ap;
    int K, lda;
    if (MODE == 0) { Ap = side ? x2 : x1; K = DIN; lda = DIN; }
    else if (MODE == 1) { Ap = g_H1[side]; K = DH; lda = DH; }
    else { Ap = g_D2[side]; K = DH; lda = DH; }

    const int ar = tid >> 3;
    const int ac4 = (tid & 7) << 2;
    const int T = K / 32;

    float4 ra, rb0, rb1;

    auto load_t = [&](int t) {
        int k0 = t * 32;
        const float* pa = &Ap[(i0 + ar) * lda + k0 + ac4];
        ra = (MODE == 0) ? *(const float4*)pa : __ldcg((const float4*)pa);
        if (MODE == 2) {
            int r0 = tid >> 3, r1 = r0 + 32;
            rb0 = *(const float4*)&W2[(n0 + r0) * DH + k0 + ac4];
            rb1 = *(const float4*)&W2[(n0 + r1) * DH + k0 + ac4];
        } else {
            const float* __restrict__ Bp = (MODE == 0) ? W1 : W2;
            int kk0 = tid >> 4, j4 = (tid & 15) << 2;
            rb0 = *(const float4*)&Bp[(k0 + kk0) * DH + n0 + j4];
            rb1 = *(const float4*)&Bp[(k0 + kk0 + 16) * DH + n0 + j4];
        }
    };
    auto store_t = [&](int buf) {
        float* A0 = &As[buf * 32 * 34];
        A0[(ac4 + 0) * 34 + ar] = ra.x;
        A0[(ac4 + 1) * 34 + ar] = ra.y;
        A0[(ac4 + 2) * 34 + ar] = ra.z;
        A0[(ac4 + 3) * 34 + ar] = ra.w;
        float* B0 = &Bs[buf * 32 * 68];
        if (MODE == 2) {
            int r0 = tid >> 3, r1 = r0 + 32;
            B0[(ac4 + 0) * 68 + r0] = rb0.x; B0[(ac4 + 1) * 68 + r0] = rb0.y;
            B0[(ac4 + 2) * 68 + r0] = rb0.z; B0[(ac4 + 3) * 68 + r0] = rb0.w;
            B0[(ac4 + 0) * 68 + r1] = rb1.x; B0[(ac4 + 1) * 68 + r1] = rb1.y;
            B0[(ac4 + 2) * 68 + r1] = rb1.z; B0[(ac4 + 3) * 68 + r1] = rb1.w;
        } else {
            int kk0 = tid >> 4, j4 = (tid & 15) << 2;
            *(float4*)&B0[kk0 * 68 + j4] = rb0;
            *(float4*)&B0[(kk0 + 16) * 68 + j4] = rb1;
        }
    };

    float acc[8] = {};

    load_t(0); store_t(0); __syncthreads();
    for (int t = 0; t < T; t++) {
        if (t + 1 < T) load_t(t + 1);
        int b = t & 1;
#pragma unroll
        for (int kk = 0; kk < 32; kk++) {
            float2 a = *(const float2*)&As[(b * 32 + kk) * 34 + ti * 2];
            float4 bb = *(const float4*)&Bs[(b * 32 + kk) * 68 + tj * 4];
            acc[0] = fmaf(a.x, bb.x, acc[0]);
            acc[1] = fmaf(a.x, bb.y, acc[1]);
            acc[2] = fmaf(a.x, bb.z, acc[2]);
            acc[3] = fmaf(a.x, bb.w, acc[3]);
            acc[4] = fmaf(a.y, bb.x, acc[4]);
            acc[5] = fmaf(a.y, bb.y, acc[5]);
            acc[6] = fmaf(a.y, bb.z, acc[6]);
            acc[7] = fmaf(a.y, bb.w, acc[7]);
        }
        if (t + 1 < T) store_t((t + 1) & 1);
        __syncthreads();
    }

    const int col = n0 + tj * 4;
    if (MODE == 0) {
        float4 bias = *(const float4*)&b1[col];
#pragma unroll
        for (int r = 0; r < 2; r++) {
            float4 o;
            o.x = fmaxf(acc[r * 4 + 0] + bias.x, 0.0f);
            o.y = fmaxf(acc[r * 4 + 1] + bias.y, 0.0f);
            o.z = fmaxf(acc[r * 4 + 2] + bias.z, 0.0f);
            o.w = fmaxf(acc[r * 4 + 3] + bias.w, 0.0f);
            int off = (i0 + ti * 2 + r) * DH + col;
            *(float4*)&g_H1[side][off] = o;
            split4(o, g_Fhi[1][side], g_Flo[1][side], off);
        }
        if ((rem & 3) == 0) {
            for (int e = tid; e < 32 * DIN; e += NTH) {
                int r = e >> 7, cc = e & (DIN - 1);
                float v = Ap[(i0 + r) * DIN + cc];
                split1(v, g_Fhi[0][side], g_Flo[0][side], (i0 + r) * DH + cc);
            }
        }
    } else if (MODE == 1) {
        float4 bias = *(const float4*)&b2[col];
        float w3c[4];
#pragma unroll
        for (int c = 0; c < 4; c++) w3c[c] = W3[(col + c) * 10 + COUT];
        float bv[4] = {bias.x, bias.y, bias.z, bias.w};
#pragma unroll
        for (int r = 0; r < 2; r++) {
            float a0 = acc[r * 4 + 0] + bv[0];
            float a1 = acc[r * 4 + 1] + bv[1];
            float a2 = acc[r * 4 + 2] + bv[2];
            float a3 = acc[r * 4 + 3] + bv[3];
            float4 h, d;
            h.x = fmaxf(a0, 0.0f); d.x = a0 > 0.0f ? w3c[0] : 0.0f;
            h.y = fmaxf(a1, 0.0f); d.y = a1 > 0.0f ? w3c[1] : 0.0f;
            h.z = fmaxf(a2, 0.0f); d.z = a2 > 0.0f ? w3c[2] : 0.0f;
            h.w = fmaxf(a3, 0.0f); d.w = a3 > 0.0f ? w3c[3] : 0.0f;
            int off = (i0 + ti * 2 + r) * DH + col;
            *(float4*)&g_H2[side][off] = h;
            *(float4*)&g_D2[side][off] = d;
            split4(h, g_Fhi[2][side], g_Flo[2][side], off);
            split4(d, g_Fhi[4][side], g_Flo[4][side], off);
        }
    } else {
#pragma unroll
        for (int r = 0; r < 2; r++) {
            int off = (i0 + ti * 2 + r) * DH + col;
            float4 h1 = __ldcg((const float4*)&g_H1[side][off]);
            float4 o;
            o.x = h1.x > 0.0f ? acc[r * 4 + 0] : 0.0f;
            o.y = h1.y > 0.0f ? acc[r * 4 + 1] : 0.0f;
            o.z = h1.z > 0.0f ? acc[r * 4 + 2] : 0.0f;
            o.w = h1.w > 0.0f ? acc[r * 4 + 3] : 0.0f;
            *(float4*)&g_D1[side][off] = o;
            split4(o, g_Fhi[3][side], g_Flo[3][side], off);
        }
    }
}

// ===========================================================================
// Gram tile: 128x64, 8 warps (4x2 of 32x32), bf16 3-pass, single smem buffer
// with register prefetch. 160 tiles: g=w>>5, t=w&31, i0=(t>>3)*128, j0=(t&7)*64
// ===========================================================================
#define LDSM4(r, p) do { \
    unsigned _a = (unsigned)__cvta_generic_to_shared(p); \
    asm volatile("ldmatrix.sync.aligned.m8n8.x4.shared.b16 {%0,%1,%2,%3}, [%4];" \
        : "=r"((r)[0]), "=r"((r)[1]), "=r"((r)[2]), "=r"((r)[3]) : "r"(_a)); \
} while (0)

#define MMA_BF16(ac, a, b0, b1) \
    asm volatile("mma.sync.aligned.m16n8k16.row.col.f32.bf16.bf16.f32 " \
        "{%0,%1,%2,%3}, {%4,%5,%6,%7}, {%8,%9}, {%0,%1,%2,%3};" \
        : "+f"((ac)[0]), "+f"((ac)[1]), "+f"((ac)[2]), "+f"((ac)[3]) \
        : "r"((a)[0]), "r"((a)[1]), "r"((a)[2]), "r"((a)[3]), "r"(b0), "r"(b1))

__device__ void gram_tile(char* sm, int w)
{
    const int tid = threadIdx.x;
    const int warp = tid >> 5, lane = tid & 31;
    const int g = w >> 5;
    const int t = w & 31;
    const int i0 = (t >> 3) * 128, j0 = (t & 7) * 64;
    const int chunks = (g == 0) ? 4 : 8;

    __nv_bfloat16* Ah = (__nv_bfloat16*)sm;               // [128][40] 10240B
    __nv_bfloat16* Al = (__nv_bfloat16*)(sm + 10240);     // [128][40]
    __nv_bfloat16* Bh = (__nv_bfloat16*)(sm + 20480);     // [64][40]  5120B
    __nv_bfloat16* Bl = (__nv_bfloat16*)(sm + 25600);     // [64][40]

    const __nv_bfloat16* __restrict__ pAh = g_Fhi[g][0];
    const __nv_bfloat16* __restrict__ pAl = g_Flo[g][0];
    const __nv_bfloat16* __restrict__ pBh = g_Fhi[g][1];
    const __nv_bfloat16* __restrict__ pBl = g_Flo[g][1];

    uint4 rah[2], ral[2], rbh, rbl;
    auto fill_load = [&](int c) {
        int k0 = c * 32;
#pragma unroll
        for (int q = 0; q < 2; q++) {
            int idx = tid + q * 256;
            int r = idx >> 2, ck = (idx & 3) * 8;
            rah[q] = __ldcg((const uint4*)&pAh[(i0 + r) * DH + k0 + ck]);
            ral[q] = __ldcg((const uint4*)&pAl[(i0 + r) * DH + k0 + ck]);
        }
        int rb = tid >> 2, ckb = (tid & 3) * 8;
        rbh = __ldcg((const uint4*)&pBh[(j0 + rb) * DH + k0 + ckb]);
        rbl = __ldcg((const uint4*)&pBl[(j0 + rb) * DH + k0 + ckb]);
    };
    auto fill_store = [&]() {
#pragma unroll
        for (int q = 0; q < 2; q++) {
            int idx = tid + q * 256;
            int r = idx >> 2, ck = (idx & 3) * 8;
            *(uint4*)&Ah[r * 40 + ck] = rah[q];
            *(uint4*)&Al[r * 40 + ck] = ral[q];
        }
        int rb = tid >> 2, ckb = (tid & 3) * 8;
        *(uint4*)&Bh[rb * 40 + ckb] = rbh;
        *(uint4*)&Bl[rb * 40 + ckb] = rbl;
    };

    const int wy = warp >> 1, wx = warp & 1;
    const int a_base = wy * 32 + ((lane >> 3) & 1) * 8 + (lane & 7);
    const int a_cb = (lane >> 4) * 8;
    const int b_base = wx * 32 + (lane >> 4) * 8 + (lane & 7);
    const int b_cb = ((lane >> 3) & 1) * 8;

    float acc[2][4][4] = {};

    fill_load(0);
    fill_store();
    __syncthreads();

    for (int c = 0; c < chunks; c++) {
        if (c + 1 < chunks) fill_load(c + 1);
#pragma unroll
        for (int ks = 0; ks < 2; ks++) {
            unsigned ah[2][4], al[2][4], bh[2][4], bl[2][4];
#pragma unroll
            for (int rf = 0; rf < 2; rf++) {
                LDSM4(ah[rf], &Ah[(a_base + rf * 16) * 40 + a_cb + ks * 16]);
                LDSM4(al[rf], &Al[(a_base + rf * 16) * 40 + a_cb + ks * 16]);
                LDSM4(bh[rf], &Bh[(b_base + rf * 16) * 40 + b_cb + ks * 16]);
                LDSM4(bl[rf], &Bl[(b_base + rf * 16) * 40 + b_cb + ks * 16]);
            }
#pragma unroll
            for (int rf = 0; rf < 2; rf++) {
                MMA_BF16(acc[rf][0], ah[rf], bh[0][0], bh[0][1]);
                MMA_BF16(acc[rf][1], ah[rf], bh[0][2], bh[0][3]);
                MMA_BF16(acc[rf][2], ah[rf], bh[1][0], bh[1][1]);
                MMA_BF16(acc[rf][3], ah[rf], bh[1][2], bh[1][3]);
                MMA_BF16(acc[rf][0], ah[rf], bl[0][0], bl[0][1]);
                MMA_BF16(acc[rf][1], ah[rf], bl[0][2], bl[0][3]);
                MMA_BF16(acc[rf][2], ah[rf], bl[1][0], bl[1][1]);
                MMA_BF16(acc[rf][3], ah[rf], bl[1][2], bl[1][3]);
                MMA_BF16(acc[rf][0], al[rf], bh[0][0], bh[0][1]);
                MMA_BF16(acc[rf][1], al[rf], bh[0][2], bh[0][3]);
                MMA_BF16(acc[rf][2], al[rf], bh[1][0], bh[1][1]);
                MMA_BF16(acc[rf][3], al[rf], bh[1][2], bh[1][3]);
            }
        }
        __syncthreads();
        if (c + 1 < chunks) {
            fill_store();
            __syncthreads();
        }
    }

    const int g4 = lane >> 2, tg = lane & 3;
#pragma unroll
    for (int rf = 0; rf < 2; rf++) {
        int row = i0 + wy * 32 + rf * 16 + g4;
#pragma unroll
        for (int nf = 0; nf < 4; nf++) {
            int col = j0 + wx * 32 + nf * 8 + tg * 2;
            *(float2*)&g_S[g][row * NB + col] =
                make_float2(acc[rf][nf][0], acc[rf][nf][1]);
            *(float2*)&g_S[g][(row + 8) * NB + col] =
                make_float2(acc[rf][nf][2], acc[rf][nf][3]);
        }
    }
}

// ===========================================================================
// Norms: chunk c in [0,32), 32 samples per chunk, 8 lanes per sample.
// ===========================================================================
__device__ void norms_chunk(int c, const float* __restrict__ x1,
                            const float* __restrict__ x2)
{
    const int tid = threadIdx.x;
    const int warp = tid >> 5, lane = tid & 31;
    const int s = c * 32 + warp * 4 + (lane >> 3);
    const int side = s >> 9, i = s & (NB - 1);
    const int l = lane & 7;
    const float* __restrict__ X = side ? x2 : x1;

    float sx = 0.0f;
#pragma unroll
    for (int q = 0; q < 4; q++)
        sx += sq4(*(const float4*)&X[i * DIN + (l + q * 8) * 4]);
    float sh1 = 0, sh2 = 0, sd1 = 0, sd2 = 0;
#pragma unroll
    for (int q = 0; q < 8; q++) {
        int off = i * DH + (l + q * 8) * 4;
        sh1 += sq4(__ldcg((const float4*)&g_H1[side][off]));
        sh2 += sq4(__ldcg((const float4*)&g_H2[side][off]));
        sd1 += sq4(__ldcg((const float4*)&g_D1[side][off]));
        sd2 += sq4(__ldcg((const float4*)&g_D2[side][off]));
    }
#pragma unroll
    for (int o = 4; o > 0; o >>= 1) {
        sx  += __shfl_down_sync(0xffffffffu, sx, o, 8);
        sh1 += __shfl_down_sync(0xffffffffu, sh1, o, 8);
        sh2 += __shfl_down_sync(0xffffffffu, sh2, o, 8);
        sd1 += __shfl_down_sync(0xffffffffu, sd1, o, 8);
        sd2 += __shfl_down_sync(0xffffffffu, sd2, o, 8);
    }
    if (l == 0) {
        float n2 = (1.0f + sx) * sd1 + (1.0f + sh1) * sd2 + 1.0f + sh2;
        g_invn[side][i] = rsqrtf(n2);
    }
}

// ===========================================================================
// Fused persistent kernel: 164 CTAs x 256 threads.
// ===========================================================================
__global__ void __launch_bounds__(NTH, 2)
fused_kernel(const float* __restrict__ x1, const float* __restrict__ x2,
             const float* __restrict__ W1, const float* __restrict__ b1,
             const float* __restrict__ W2, const float* __restrict__ b2,
             const float* __restrict__ W3, float* __restrict__ out)
{
    __shared__ __align__(16) char sm[30720];
    const int cta = blockIdx.x;
    const int tid = threadIdx.x;

    feat_phase<0>(sm, cta, x1, x2, W1, b1, W2, b2, W3);
    gbar(0);
    feat_phase<1>(sm, cta, x1, x2, W1, b1, W2, b2, W3);
    gbar(1);
    feat_phase<2>(sm, cta, x1, x2, W1, b1, W2, b2, W3);
    gbar(2);
    // 160 gram tiles + 32 norm chunks
    for (int w = cta; w < 192; w += GRID) {
        __syncthreads();
        if (w < 160) gram_tile(sm, w);
        else norms_chunk(w - 160, x1, x2);
    }
    gbar(3);
    // combine + normalize
    for (int e4 = cta * NTH + tid; e4 < NB * NB / 4; e4 += GRID * NTH) {
        int e = e4 * 4;
        int i = e >> 9;
        int j = e & (NB - 1);
        float4 sx  = __ldcg((const float4*)&g_S[0][e]);
        float4 sh1 = __ldcg((const float4*)&g_S[1][e]);
        float4 sh2 = __ldcg((const float4*)&g_S[2][e]);
        float4 sd1 = __ldcg((const float4*)&g_S[3][e]);
        float4 sd2 = __ldcg((const float4*)&g_S[4][e]);
        float ni = __ldcg(&g_invn[0][i]);
        float4 nj = __ldcg((const float4*)&g_invn[1][j]);

        float4 o;
        o.x = ((1.0f + sx.x) * sd1.x + (1.0f + sh1.x) * sd2.x + 1.0f + sh2.x) * ni * nj.x;
        o.y = ((1.0f + sx.y) * sd1.y + (1.0f + sh1.y) * sd2.y + 1.0f + sh2.y) * ni * nj.y;
        o.z = ((1.0f + sx.z) * sd1.z + (1.0f + sh1.z) * sd2.z + 1.0f + sh2.z) * ni * nj.z;
        o.w = ((1.0f + sx.w) * sd1.w + (1.0f + sh1.w) * sd2.w + 1.0f + sh2.w) * ni * nj.w;
        *(float4*)&out[e] = o;
    }
}

// ===========================================================================
extern "C" void kernel_launch(void* const* d_in, const int* in_sizes, int n_in,
                              void* d_out, int out_size)
{
    const float* x1 = (const float*)d_in[0];
    const float* x2 = (const float*)d_in[1];
    const float* W1 = (const float*)d_in[2];
    const float* b1 = (const float*)d_in[3];
    const float* W2 = (const float*)d_in[4];
    const float* b2 = (const float*)d_in[5];
    const float* W3 = (const float*)d_in[6];
    float* out = (float*)d_out;

    fused_kernel<<<GRID, NTH>>>(x1, x2, W1, b1, W2, b2, W3, out);
}

// round 13
// speedup vs baseline: 1.2161x; 1.2161x over previous
#include <cuda_runtime.h>
#include <cuda_bf16.h>

#define NB    512
#define DIN   128
#define DH    256
#define COUT  0

// Scratch (fp32 features)
__device__ float g_H1[2][NB * DH];
__device__ float g_H2[2][NB * DH];
__device__ float g_D1[2][NB * DH];
__device__ float g_D2[2][NB * DH];
__device__ float g_invn[2][NB];
__device__ float g_S[5][NB * NB];   // 0:Sx 1:Sh1 2:Sh2 3:Sd1 4:Sd2

// ===========================================================================
// Feature GEMMs (proven scalar R4/R7 body): 32x64 tile, KT=32, micro 2x4.
// ===========================================================================
template <int MODE>
__global__ void __launch_bounds__(256)
feat_gemm(const float* __restrict__ x1, const float* __restrict__ x2,
          const float* __restrict__ W1, const float* __restrict__ b1,
          const float* __restrict__ W2, const float* __restrict__ b2,
          const float* __restrict__ W3)
{
    __shared__ float As[2][32][34];
    __shared__ float Bs[2][32][68];

    const int side = blockIdx.z;
    const int i0 = blockIdx.x * 32;
    const int n0 = blockIdx.y * 64;
    const int tid = threadIdx.x;
    const int ti = tid >> 4;
    const int tj = tid & 15;

    const float* __restrict__ Ap;
    int K, lda;
    if (MODE == 0) { Ap = side ? x2 : x1; K = DIN; lda = DIN; }
    else if (MODE == 1) { Ap = g_H1[side]; K = DH; lda = DH; }
    else { Ap = g_D2[side]; K = DH; lda = DH; }

    const int ar = tid >> 3;
    const int ac4 = (tid & 7) << 2;
    const int T = K / 32;

    float4 ra, rb0, rb1;

    auto load_tiles = [&](int t) {
        int k0 = t * 32;
        ra = *(const float4*)&Ap[(i0 + ar) * lda + k0 + ac4];
        if (MODE == 2) {
            int r0 = tid >> 3, r1 = r0 + 32;
            rb0 = *(const float4*)&W2[(n0 + r0) * DH + k0 + ac4];
            rb1 = *(const float4*)&W2[(n0 + r1) * DH + k0 + ac4];
        } else {
            const float* __restrict__ Bp = (MODE == 0) ? W1 : W2;
            int kk0 = tid >> 4, j4 = (tid & 15) << 2;
            rb0 = *(const float4*)&Bp[(k0 + kk0) * DH + n0 + j4];
            rb1 = *(const float4*)&Bp[(k0 + kk0 + 16) * DH + n0 + j4];
        }
    };
    auto store_tiles = [&](int buf) {
        As[buf][ac4 + 0][ar] = ra.x;
        As[buf][ac4 + 1][ar] = ra.y;
        As[buf][ac4 + 2][ar] = ra.z;
        As[buf][ac4 + 3][ar] = ra.w;
        if (MODE == 2) {
            int r0 = tid >> 3, r1 = r0 + 32;
            Bs[buf][ac4 + 0][r0] = rb0.x; Bs[buf][ac4 + 1][r0] = rb0.y;
            Bs[buf][ac4 + 2][r0] = rb0.z; Bs[buf][ac4 + 3][r0] = rb0.w;
            Bs[buf][ac4 + 0][r1] = rb1.x; Bs[buf][ac4 + 1][r1] = rb1.y;
            Bs[buf][ac4 + 2][r1] = rb1.z; Bs[buf][ac4 + 3][r1] = rb1.w;
        } else {
            int kk0 = tid >> 4, j4 = (tid & 15) << 2;
            *(float4*)&Bs[buf][kk0][j4] = rb0;
            *(float4*)&Bs[buf][kk0 + 16][j4] = rb1;
        }
    };

    float acc[8] = {};

    load_tiles(0);
    store_tiles(0);
    __syncthreads();

    for (int t = 0; t < T; t++) {
        if (t + 1 < T) load_tiles(t + 1);
        int b = t & 1;
#pragma unroll
        for (int kk = 0; kk < 32; kk++) {
            float2 a = *(const float2*)&As[b][kk][ti * 2];
            float4 bb = *(const float4*)&Bs[b][kk][tj * 4];
            acc[0] = fmaf(a.x, bb.x, acc[0]);
            acc[1] = fmaf(a.x, bb.y, acc[1]);
            acc[2] = fmaf(a.x, bb.z, acc[2]);
            acc[3] = fmaf(a.x, bb.w, acc[3]);
            acc[4] = fmaf(a.y, bb.x, acc[4]);
            acc[5] = fmaf(a.y, bb.y, acc[5]);
            acc[6] = fmaf(a.y, bb.z, acc[6]);
            acc[7] = fmaf(a.y, bb.w, acc[7]);
        }
        if (t + 1 < T) store_tiles((t + 1) & 1);
        __syncthreads();
    }

    const int col = n0 + tj * 4;
    if (MODE == 0) {
        float4 bias = *(const float4*)&b1[col];
#pragma unroll
        for (int r = 0; r < 2; r++) {
            float4 o;
            o.x = fmaxf(acc[r * 4 + 0] + bias.x, 0.0f);
            o.y = fmaxf(acc[r * 4 + 1] + bias.y, 0.0f);
            o.z = fmaxf(acc[r * 4 + 2] + bias.z, 0.0f);
            o.w = fmaxf(acc[r * 4 + 3] + bias.w, 0.0f);
            *(float4*)&g_H1[side][(i0 + ti * 2 + r) * DH + col] = o;
        }
    } else if (MODE == 1) {
        float4 bias = *(const float4*)&b2[col];
        float4 w3c;
        w3c.x = W3[(col + 0) * 10 + COUT];
        w3c.y = W3[(col + 1) * 10 + COUT];
        w3c.z = W3[(col + 2) * 10 + COUT];
        w3c.w = W3[(col + 3) * 10 + COUT];
#pragma unroll
        for (int r = 0; r < 2; r++) {
            float a0 = acc[r * 4 + 0] + bias.x;
            float a1 = acc[r * 4 + 1] + bias.y;
            float a2 = acc[r * 4 + 2] + bias.z;
            float a3 = acc[r * 4 + 3] + bias.w;
            float4 h, d;
            h.x = fmaxf(a0, 0.0f); d.x = a0 > 0.0f ? w3c.x : 0.0f;
            h.y = fmaxf(a1, 0.0f); d.y = a1 > 0.0f ? w3c.y : 0.0f;
            h.z = fmaxf(a2, 0.0f); d.z = a2 > 0.0f ? w3c.z : 0.0f;
            h.w = fmaxf(a3, 0.0f); d.w = a3 > 0.0f ? w3c.w : 0.0f;
            int off = (i0 + ti * 2 + r) * DH + col;
            *(float4*)&g_H2[side][off] = h;
            *(float4*)&g_D2[side][off] = d;
        }
    } else {
#pragma unroll
        for (int r = 0; r < 2; r++) {
            int off = (i0 + ti * 2 + r) * DH + col;
            float4 h1 = *(const float4*)&g_H1[side][off];
            float4 o;
            o.x = h1.x > 0.0f ? acc[r * 4 + 0] : 0.0f;
            o.y = h1.y > 0.0f ? acc[r * 4 + 1] : 0.0f;
            o.z = h1.z > 0.0f ? acc[r * 4 + 2] : 0.0f;
            o.w = h1.w > 0.0f ? acc[r * 4 + 3] : 0.0f;
            *(float4*)&g_D1[side][off] = o;
        }
    }
}

// ===========================================================================
// TF32 single-pass Gram + folded norms. grid (8,8,6), 128 threads.
// 64x64 tile, 4 warps of 32x32, K-chunk 32, double-buffered.
// ===========================================================================
#define LDSM4(r, p) do { \
    unsigned _a = (unsigned)__cvta_generic_to_shared(p); \
    asm volatile("ldmatrix.sync.aligned.m8n8.x4.shared.b16 {%0,%1,%2,%3}, [%4];" \
        : "=r"((r)[0]), "=r"((r)[1]), "=r"((r)[2]), "=r"((r)[3]) : "r"(_a)); \
} while (0)

#define LDSM2(r, p) do { \
    unsigned _a = (unsigned)__cvta_generic_to_shared(p); \
    asm volatile("ldmatrix.sync.aligned.m8n8.x2.shared.b16 {%0,%1}, [%2];" \
        : "=r"((r)[0]), "=r"((r)[1]) : "r"(_a)); \
} while (0)

#define MMA_TF32(ac, a, b0, b1) \
    asm volatile("mma.sync.aligned.m16n8k8.row.col.f32.tf32.tf32.f32 " \
        "{%0,%1,%2,%3}, {%4,%5,%6,%7}, {%8,%9}, {%0,%1,%2,%3};" \
        : "+f"((ac)[0]), "+f"((ac)[1]), "+f"((ac)[2]), "+f"((ac)[3]) \
        : "r"((a)[0]), "r"((a)[1]), "r"((a)[2]), "r"((a)[3]), "r"(b0), "r"(b1))

__device__ __forceinline__ unsigned f2tf(float f) {
    unsigned r;
    asm("cvt.rna.tf32.f32 %0, %1;" : "=r"(r) : "f"(f));
    return r;
}

__device__ __forceinline__ uint4 cvt4(float4 v) {
    uint4 u;
    u.x = f2tf(v.x); u.y = f2tf(v.y); u.z = f2tf(v.z); u.w = f2tf(v.w);
    return u;
}

__device__ __forceinline__ float sq4(float4 v) {
    return fmaf(v.x, v.x, fmaf(v.y, v.y, fmaf(v.z, v.z, v.w * v.w)));
}

__global__ void __launch_bounds__(128)
gram_tf32(const float* __restrict__ x1, const float* __restrict__ x2)
{
    const int z = blockIdx.z;
    const int tid = threadIdx.x;
    const int warp = tid >> 5, lane = tid & 31;

    if (z == 5) {
        // ---- norms: 64 CTAs x 16 samples; 8 lanes per sample ----
        const int cta = blockIdx.y * 8 + blockIdx.x;
        const int s = cta * 16 + warp * 4 + (lane >> 3);
        const int side = s >> 9, i = s & (NB - 1);
        const int l = lane & 7;
        const float* __restrict__ X = side ? x2 : x1;

        float sx = 0.0f;
#pragma unroll
        for (int q = 0; q < 4; q++)
            sx += sq4(*(const float4*)&X[i * DIN + (l + q * 8) * 4]);
        float sh1 = 0, sh2 = 0, sd1 = 0, sd2 = 0;
#pragma unroll
        for (int q = 0; q < 8; q++) {
            int off = i * DH + (l + q * 8) * 4;
            sh1 += sq4(*(const float4*)&g_H1[side][off]);
            sh2 += sq4(*(const float4*)&g_H2[side][off]);
            sd1 += sq4(*(const float4*)&g_D1[side][off]);
            sd2 += sq4(*(const float4*)&g_D2[side][off]);
        }
#pragma unroll
        for (int o = 4; o > 0; o >>= 1) {
            sx  += __shfl_down_sync(0xffffffffu, sx, o, 8);
            sh1 += __shfl_down_sync(0xffffffffu, sh1, o, 8);
            sh2 += __shfl_down_sync(0xffffffffu, sh2, o, 8);
            sd1 += __shfl_down_sync(0xffffffffu, sd1, o, 8);
            sd2 += __shfl_down_sync(0xffffffffu, sd2, o, 8);
        }
        if (l == 0) {
            float n2 = (1.0f + sx) * sd1 + (1.0f + sh1) * sd2 + 1.0f + sh2;
            g_invn[side][i] = rsqrtf(n2);
        }
        return;
    }

    // ---- tf32 gram: 64x64 tile ----
    __shared__ alignas(16) float As[2][64][36];
    __shared__ alignas(16) float Bs[2][64][36];

    const int i0 = blockIdx.x * 64, j0 = blockIdx.y * 64;
    const float* A;
    const float* B;
    int K, lda;
    switch (z) {
        case 0: A = x1;       B = x2;       K = DIN; lda = DIN; break;
        case 1: A = g_H1[0];  B = g_H1[1];  K = DH;  lda = DH;  break;
        case 2: A = g_H2[0];  B = g_H2[1];  K = DH;  lda = DH;  break;
        case 3: A = g_D1[0];  B = g_D1[1];  K = DH;  lda = DH;  break;
        default:A = g_D2[0];  B = g_D2[1];  K = DH;  lda = DH;  break;
    }
    const int chunks = K / 32;

    // fill: 64 rows x 32 floats per matrix = 512 float4; 4 per thread
    float4 ra[4], rb[4];
    auto load_tiles = [&](int c) {
        int k0 = c * 32;
#pragma unroll
        for (int q = 0; q < 4; q++) {
            int idx = tid + q * 128;
            int r = idx >> 3, c4 = (idx & 7) * 4;
            ra[q] = *(const float4*)&A[(i0 + r) * lda + k0 + c4];
            rb[q] = *(const float4*)&B[(j0 + r) * lda + k0 + c4];
        }
    };
    auto store_tiles = [&](int b) {
#pragma unroll
        for (int q = 0; q < 4; q++) {
            int idx = tid + q * 128;
            int r = idx >> 3, c4 = (idx & 7) * 4;
            *(uint4*)&As[b][r][c4] = cvt4(ra[q]);
            *(uint4*)&Bs[b][r][c4] = cvt4(rb[q]);
        }
    };

    // warp 2x2 grid, each 32x32
    const int wy = warp >> 1, wx = warp & 1;
    // A frag addresses (x4 over 16 rows x 32B): per rf block of 16 rows
    const int a_row_off = ((lane >> 3) & 1) * 8 + (lane & 7);
    const int a_cf = (lane >> 4) * 4;
    // B frag addresses (x2 over 8 rows x 32B), lanes 0-15 supply addrs
    const int b_row_off = lane & 7;
    const int b_cf = ((lane >> 3) & 1) * 4;

    float acc[2][4][4] = {};

    load_tiles(0);
    store_tiles(0);
    __syncthreads();

    for (int c = 0; c < chunks; c++) {
        if (c + 1 < chunks) load_tiles(c + 1);
        int b = c & 1;
#pragma unroll
        for (int ks = 0; ks < 4; ks++) {
            unsigned af[2][4], bf[4][2];
#pragma unroll
            for (int rf = 0; rf < 2; rf++)
                LDSM4(af[rf], &As[b][wy * 32 + rf * 16 + a_row_off][ks * 8 + a_cf]);
#pragma unroll
            for (int nf = 0; nf < 4; nf++)
                LDSM2(bf[nf], &Bs[b][wx * 32 + nf * 8 + b_row_off][ks * 8 + b_cf]);
#pragma unroll
            for (int rf = 0; rf < 2; rf++) {
                MMA_TF32(acc[rf][0], af[rf], bf[0][0], bf[0][1]);
                MMA_TF32(acc[rf][1], af[rf], bf[1][0], bf[1][1]);
                MMA_TF32(acc[rf][2], af[rf], bf[2][0], bf[2][1]);
                MMA_TF32(acc[rf][3], af[rf], bf[3][0], bf[3][1]);
            }
        }
        if (c + 1 < chunks) store_tiles((c + 1) & 1);
        __syncthreads();
    }

    const int g4 = lane >> 2, tg = lane & 3;
#pragma unroll
    for (int rf = 0; rf < 2; rf++) {
        int row = i0 + wy * 32 + rf * 16 + g4;
#pragma unroll
        for (int nf = 0; nf < 4; nf++) {
            int col = j0 + wx * 32 + nf * 8 + tg * 2;
            *(float2*)&g_S[z][row * NB + col] =
                make_float2(acc[rf][nf][0], acc[rf][nf][1]);
            *(float2*)&g_S[z][(row + 8) * NB + col] =
                make_float2(acc[rf][nf][2], acc[rf][nf][3]);
        }
    }
}

// ===========================================================================
// Elementwise combine + normalize.
// ===========================================================================
__global__ void __launch_bounds__(256)
combine_kernel(float* __restrict__ out)
{
    const int e = (blockIdx.x * 256 + threadIdx.x) * 4;
    const int i = e >> 9;
    const int j = e & (NB - 1);

    float4 sx  = *(const float4*)&g_S[0][e];
    float4 sh1 = *(const float4*)&g_S[1][e];
    float4 sh2 = *(const float4*)&g_S[2][e];
    float4 sd1 = *(const float4*)&g_S[3][e];
    float4 sd2 = *(const float4*)&g_S[4][e];
    float ni = g_invn[0][i];
    float4 nj = *(const float4*)&g_invn[1][j];

    float4 o;
    o.x = ((1.0f + sx.x) * sd1.x + (1.0f + sh1.x) * sd2.x + 1.0f + sh2.x) * ni * nj.x;
    o.y = ((1.0f + sx.y) * sd1.y + (1.0f + sh1.y) * sd2.y + 1.0f + sh2.y) * ni * nj.y;
    o.z = ((1.0f + sx.z) * sd1.z + (1.0f + sh1.z) * sd2.z + 1.0f + sh2.z) * ni * nj.z;
    o.w = ((1.0f + sx.w) * sd1.w + (1.0f + sh1.w) * sd2.w + 1.0f + sh2.w) * ni * nj.w;
    *(float4*)&out[e] = o;
}

// ===========================================================================
extern "C" void kernel_launch(void* const* d_in, const int* in_sizes, int n_in,
                              void* d_out, int out_size)
{
    const float* x1 = (const float*)d_in[0];
    const float* x2 = (const float*)d_in[1];
    const float* W1 = (const float*)d_in[2];
    const float* b1 = (const float*)d_in[3];
    const float* W2 = (const float*)d_in[4];
    const float* b2 = (const float*)d_in[5];
    const float* W3 = (const float*)d_in[6];
    float* out = (float*)d_out;

    feat_gemm<0><<<dim3(16, 4, 2), 256>>>(x1, x2, W1, b1, W2, b2, W3);
    feat_gemm<1><<<dim3(16, 4, 2), 256>>>(x1, x2, W1, b1, W2, b2, W3);
    feat_gemm<2><<<dim3(16, 4, 2), 256>>>(x1, x2, W1, b1, W2, b2, W3);
    gram_tf32<<<dim3(8, 8, 6), 128>>>(x1, x2);
    combine_kernel<<<256, 256>>>(out);
}